// round 16
// baseline (speedup 1.0000x reference)
#include <cuda_runtime.h>
#include <cuda_bf16.h>
#include <cstdint>

// ESN: h_t = tanh(x_t @ W_in^T + h_{t-1} @ W_res^T); out = h_{T-1} [B,H] fp32.
// B=64, T=512, I=128, H=2048.
//
// Round 16: round-15 chassis + warp-specialized tail:
//  - warps 0-7: reduce role (per-jg hfl flags, 8 arrivals/step)
//  - warps 8-15: stager role (WAR + RAW spins, v copy)
//  run CONCURRENTLY, joined by one final __syncthreads. bid>=128 stages
//  with all 16 warps. MMA/producer path identical to round 15.

#define BB   64
#define TT   512
#define II   128
#define HH   2048
#define NJG  16
#define NKS  9
#define KC1  256
#define NTHR 512
#define NCTA (NJG * NKS)          // 144
#define ASTRIDE 528               // bytes per j-row of W tiles (512 + 16 pad)
#define TSZA (128 * ASTRIDE)      // 67584 per W term
#define BSTR 144                  // bytes per k-row of v (128 data + 16 pad)
#define TSZB (256 * BSTR)         // 36864 per v term (max 256 k-rows)
#define BOFF (2 * TSZA)
#define SLOT (2 * TSZA)
#define DYN_SMEM (2 * TSZA + 2 * TSZB)   // 208896

// ---------------- device globals ----------------
struct __align__(128) PadFlag { unsigned v; unsigned pad[31]; };

__device__ __align__(16) unsigned char  g_wt[NCTA * SLOT];
__device__ __align__(16) __nv_bfloat16  g_xth[TT * II * BB];   // x^T hi: [t][k][b]
__device__ __align__(16) __nv_bfloat16  g_xtl[TT * II * BB];   // x^T lo
__device__ __align__(16) __nv_bfloat16  g_hth[2][HH * BB];     // h^T hi: [j][b]
__device__ __align__(16) __nv_bfloat16  g_htl[2][HH * BB];     // h^T lo
__device__ float    g_part[2][NKS * NJG * 128 * BB];           // ping-pong by t&1
__device__ PadFlag  g_pcnt[NJG];   // partials stored, per jg (9/step)
__device__ PadFlag  g_hfl[NJG];    // h jg-tile ready, per jg (8/step)

// ---------------- asm helpers ----------------
__device__ __forceinline__ void mma_bf16(float* d, const uint32_t* a,
                                         uint32_t b0, uint32_t b1) {
    asm volatile(
        "mma.sync.aligned.m16n8k16.row.col.f32.bf16.bf16.f32 "
        "{%0,%1,%2,%3}, {%4,%5,%6,%7}, {%8,%9}, {%0,%1,%2,%3};"
        : "+f"(d[0]), "+f"(d[1]), "+f"(d[2]), "+f"(d[3])
        : "r"(a[0]), "r"(a[1]), "r"(a[2]), "r"(a[3]), "r"(b0), "r"(b1));
}
__device__ __forceinline__ void ldmx4(uint32_t* r, uint32_t addr) {
    asm volatile("ldmatrix.sync.aligned.m8n8.x4.shared.b16 {%0,%1,%2,%3}, [%4];"
        : "=r"(r[0]), "=r"(r[1]), "=r"(r[2]), "=r"(r[3]) : "r"(addr));
}
__device__ __forceinline__ void ldmx4t(uint32_t* r, uint32_t addr) {
    asm volatile("ldmatrix.sync.aligned.m8n8.x4.trans.shared.b16 {%0,%1,%2,%3}, [%4];"
        : "=r"(r[0]), "=r"(r[1]), "=r"(r[2]), "=r"(r[3]) : "r"(addr));
}
__device__ __forceinline__ uint32_t smem_u32(const void* p) {
    uint32_t a;
    asm("{ .reg .u64 t; cvta.to.shared.u64 t, %1; cvt.u32.u64 %0, t; }"
        : "=r"(a) : "l"(p));
    return a;
}
__device__ __forceinline__ void flag_add(unsigned* p) {
    asm volatile("red.release.gpu.global.add.u32 [%0], 1;" :: "l"(p) : "memory");
}
__device__ __forceinline__ void spin_ge(unsigned* c, unsigned tgt) {
    unsigned v;
    do {
        asm volatile("ld.acquire.gpu.global.u32 %0, [%1];"
                     : "=r"(v) : "l"(c) : "memory");
    } while (v < tgt);
}
#define BAR_RED() asm volatile("bar.sync 1, 256;" ::: "memory")

// ---------------- prep ----------------
__global__ void esn_prep_w(const float* __restrict__ Win, const float* __restrict__ Wres) {
    const int total = HH * (II + HH);
    for (int idx = blockIdx.x * blockDim.x + threadIdx.x; idx < total;
         idx += gridDim.x * blockDim.x) {
        int j = idx / (II + HH);
        int k = idx % (II + HH);
        int jg = j >> 7, jl = j & 127;
        int ks, kl;
        float w;
        if (k < II) { ks = 0; kl = k; w = Win[j * II + k]; }
        else { int kk = k - II; ks = 1 + (kk >> 8); kl = kk & 255; w = Wres[j * HH + kk]; }
        __nv_bfloat16 hi = __float2bfloat16(w);
        float r = w - __bfloat162float(hi);
        __nv_bfloat16 lo = __float2bfloat16(r);
        unsigned base = (unsigned)(jg * NKS + ks) * SLOT + (unsigned)jl * ASTRIDE + (unsigned)kl * 2;
        *(__nv_bfloat16*)(g_wt + base)        = hi;
        *(__nv_bfloat16*)(g_wt + base + TSZA) = lo;
    }
}

__global__ void esn_prep_x(const float* __restrict__ x) {
    const int total = TT * II * BB;
    for (int idx = blockIdx.x * blockDim.x + threadIdx.x; idx < total;
         idx += gridDim.x * blockDim.x) {
        int b  = idx & (BB - 1);
        int tk = idx / BB;
        int t  = tk / II;
        int k  = tk % II;
        float v = x[(b * TT + t) * II + k];
        __nv_bfloat16 hi = __float2bfloat16(v);
        float r = v - __bfloat162float(hi);
        g_xth[idx] = hi;
        g_xtl[idx] = __float2bfloat16(r);
    }
}

__global__ void esn_cnt0() {
    int i = threadIdx.x;
    if (i < NJG) { g_pcnt[i].v = 0u; g_hfl[i].v = 0u; }
}

// ---------------- persistent kernel ----------------
__global__ __launch_bounds__(NTHR, 1) void esn_run(float* __restrict__ out) {
    extern __shared__ __align__(16) unsigned char sm[];

    const int tid  = threadIdx.x;
    const int wid  = tid >> 5;
    const int l    = tid & 31;
    const int wj   = wid >> 1;            // 0..7: 16-row j band
    const int wb   = wid & 1;             // 0..1: 32-col b half
    const int bid  = blockIdx.x;
    const int jg   = bid / NKS;
    const int ks   = bid % NKS;
    const int KC   = ks ? KC1 : II;
    const int kch  = KC >> 4;             // 8 or 16
    const int chunks = KC * 8;            // 16B chunks (8 per 128B k-row)
    const bool isRed = (bid < 128);

    const uint32_t smA = smem_u32(sm);
    const uint32_t smB = smA + BOFF;

    const uint32_t aA = smA + (uint32_t)(wj * 16 + ((l >> 3) & 1) * 8 + (l & 7)) * ASTRIDE
                            + (uint32_t)(l >> 4) * 16;
    const uint32_t aB = smB + (uint32_t)((l & 7) + ((l >> 3) & 1) * 8) * BSTR
                            + (uint32_t)(l >> 4) * 16 + (uint32_t)wb * 64;

    // ---- load W slot (hi + lo) into smem once ----
    {
        const uint4* src = (const uint4*)(g_wt + (unsigned)(jg * NKS + ks) * SLOT);
        uint4* dst = (uint4*)sm;
        for (int i = tid; i < SLOT / 16; i += NTHR) dst[i] = src[i];
    }

    // reduce-role constants (warps 0-7 of bid<128): 16j x 64b tile, 4 out/thread
    const int r_jg = bid >> 3;
    const int r_8  = bid & 7;
    const int jt   = (tid >> 4) & 15;      // 0..15 (valid for tid<256)
    const int b4   = (tid & 15) * 4;       // 0,4,..,60

    // stager thread-range
    const int s_base   = isRed ? 256 : 0;
    const int s_stride = isRed ? 256 : NTHR;

    // ---- stage v_0: ks==0 from x^T[0], else zeros (h_{-1} = 0) ----
    if (ks == 0) {
        for (int i = tid; i < chunks; i += NTHR) {
            int k = i >> 3, c = i & 7;
            uint32_t d = (uint32_t)(BOFF + k * BSTR + c * 16);
            int e = k * BB + c * 8;
            *(uint4*)(sm + d)        = *(const uint4*)(g_xth + e);
            *(uint4*)(sm + d + TSZB) = *(const uint4*)(g_xtl + e);
        }
    } else {
        const uint4 z = make_uint4(0u, 0u, 0u, 0u);
        for (int i = tid; i < chunks; i += NTHR) {
            int k = i >> 3, c = i & 7;
            uint32_t d = (uint32_t)(BOFF + k * BSTR + c * 16);
            *(uint4*)(sm + d)        = z;
            *(uint4*)(sm + d + TSZB) = z;
        }
    }
    __syncthreads();

    for (int t = 0; t < TT; t++) {
        // ---- MMA: all 16 warps, 16j x 32b; 3 terms ----
        float acc[4][4];
#pragma unroll
        for (int nf = 0; nf < 4; nf++)
#pragma unroll
            for (int i = 0; i < 4; i++) acc[nf][i] = 0.0f;

#pragma unroll 4
        for (int kc = 0; kc < kch; kc++) {
            const uint32_t kaA = (uint32_t)kc * 32;
            const uint32_t kaB = (uint32_t)kc * (16 * BSTR);
            uint32_t Ah[4], Al[4], Bh[2][4], Bl[2][4];
            ldmx4(Ah, aA + kaA);
            ldmx4(Al, aA + TSZA + kaA);
            ldmx4t(Bh[0], aB + kaB);
            ldmx4t(Bh[1], aB + kaB + 32);
            ldmx4t(Bl[0], aB + TSZB + kaB);
            ldmx4t(Bl[1], aB + TSZB + kaB + 32);
#pragma unroll
            for (int nf = 0; nf < 4; nf++) {
                const int ni = nf >> 1, h8 = (nf & 1) * 2;
                mma_bf16(acc[nf], Ah, Bh[ni][h8], Bh[ni][h8 + 1]);
                mma_bf16(acc[nf], Ah, Bl[ni][h8], Bl[ni][h8 + 1]);
                mma_bf16(acc[nf], Al, Bh[ni][h8], Bh[ni][h8 + 1]);
            }
        }

        // ---- partial stores (.cg): P[jl*64 + b] ----
        {
            float* P = g_part[t & 1] + (unsigned)(ks * NJG + jg) * (128 * BB);
            const int j0 = wj * 16 + (l >> 2);
            const int bc = (l & 3) * 2;
#pragma unroll
            for (int nf = 0; nf < 4; nf++) {
                const int b = wb * 32 + nf * 8 + bc;
                __stcg((float2*)&P[j0 * BB + b],       make_float2(acc[nf][0], acc[nf][1]));
                __stcg((float2*)&P[(j0 + 8) * BB + b], make_float2(acc[nf][2], acc[nf][3]));
            }
        }
        __syncthreads();                        // all P stores + all v reads done
        if (tid == 0) flag_add(&g_pcnt[jg].v);

        // ================= warp-specialized tail =================
        if (isRed && tid < 256) {
            // ---- REDUCE role: warps 0-7 ----
            spin_ge(&g_pcnt[r_jg].v, 9u * (t + 1));   // acquire orders loads

            const unsigned o = (unsigned)((r_8 * 16 + jt) * 64 + b4);
            float s[4] = {0.f, 0.f, 0.f, 0.f};
            const float* Pb = g_part[t & 1];
#pragma unroll
            for (int kr = 0; kr < NKS; kr++) {
                const float4 v = __ldcg((const float4*)
                    (Pb + (unsigned)(kr * NJG + r_jg) * (128 * BB) + o));
                s[0] += v.x; s[1] += v.y; s[2] += v.z; s[3] += v.w;
            }
#pragma unroll
            for (int i = 0; i < 4; i++) s[i] = tanhf(s[i]);

            __nv_bfloat16* hh = g_hth[t & 1];
            __nv_bfloat16* hl = g_htl[t & 1];
            const int jglob = r_jg * 128 + r_8 * 16 + jt;
            const unsigned ho = (unsigned)(jglob * BB + b4);
            __nv_bfloat162 h20 = __floats2bfloat162_rn(s[0], s[1]);
            __nv_bfloat162 h21 = __floats2bfloat162_rn(s[2], s[3]);
            float r0 = s[0] - __bfloat162float(__low2bfloat16(h20));
            float r1 = s[1] - __bfloat162float(__high2bfloat16(h20));
            float r2 = s[2] - __bfloat162float(__low2bfloat16(h21));
            float r3 = s[3] - __bfloat162float(__high2bfloat16(h21));
            __nv_bfloat162 l20 = __floats2bfloat162_rn(r0, r1);
            __nv_bfloat162 l21 = __floats2bfloat162_rn(r2, r3);
            uint2 hp = make_uint2(*(uint32_t*)&h20, *(uint32_t*)&h21);
            uint2 lp = make_uint2(*(uint32_t*)&l20, *(uint32_t*)&l21);
            __stcg((uint2*)(hh + ho), hp);
            __stcg((uint2*)(hl + ho), lp);
            if (t == TT - 1) {
#pragma unroll
                for (int i = 0; i < 4; i++)
                    out[(b4 + i) * HH + jglob] = s[i];
            }
            BAR_RED();                          // reduce warps' stores done
            if (tid == 0) flag_add(&g_hfl[r_jg].v);
        } else if (t + 1 < TT) {
            // ---- STAGER role: warps 8-15 (or all warps if bid>=128) ----
            // WAR: reducers of my jg done reading P[(t+1)&1] (step t-1)
            if (t >= 1) spin_ge(&g_hfl[jg].v, 8u * t);
            // RAW: h_t slice (two jg tiles) ready
            if (ks) {
                spin_ge(&g_hfl[2 * (ks - 1)].v,     8u * (t + 1));
                spin_ge(&g_hfl[2 * (ks - 1) + 1].v, 8u * (t + 1));
            }

            if (ks == 0) {
                const __nv_bfloat16* xh = g_xth + (t + 1) * (II * BB);
                const __nv_bfloat16* xl = g_xtl + (t + 1) * (II * BB);
                for (int i = tid - s_base; i < chunks; i += s_stride) {
                    int k = i >> 3, c = i & 7;
                    uint32_t d = (uint32_t)(BOFF + k * BSTR + c * 16);
                    int e = k * BB + c * 8;
                    *(uint4*)(sm + d)        = *(const uint4*)(xh + e);
                    *(uint4*)(sm + d + TSZB) = *(const uint4*)(xl + e);
                }
            } else {
                const __nv_bfloat16* hh = g_hth[t & 1] + (ks - 1) * (KC1 * BB);
                const __nv_bfloat16* hl = g_htl[t & 1] + (ks - 1) * (KC1 * BB);
                for (int i = tid - s_base; i < chunks; i += s_stride) {
                    int k = i >> 3, c = i & 7;
                    uint32_t d = (uint32_t)(BOFF + k * BSTR + c * 16);
                    int e = k * BB + c * 8;
                    *(uint4*)(sm + d)        = __ldcg((const uint4*)(hh + e));
                    *(uint4*)(sm + d + TSZB) = __ldcg((const uint4*)(hl + e));
                }
            }
        }
        __syncthreads();                        // join roles; v staged for next MMA
    }
}

// ---------------- launcher ----------------
extern "C" void kernel_launch(void* const* d_in, const int* in_sizes, int n_in,
                              void* d_out, int out_size)
{
    const float* x    = (const float*)d_in[0];
    const float* Win  = (const float*)d_in[1];
    const float* Wres = (const float*)d_in[2];
    float* out = (float*)d_out;

    cudaFuncSetAttribute(esn_run, cudaFuncAttributeMaxDynamicSharedMemorySize, DYN_SMEM);

    esn_prep_w<<<2048, 256>>>(Win, Wres);
    esn_prep_x<<<2048, 256>>>(x);
    esn_cnt0<<<1, 32>>>();
    esn_run<<<NCTA, NTHR, DYN_SMEM>>>(out);
}

// round 17
// speedup vs baseline: 1.0011x; 1.0011x over previous
#include <cuda_runtime.h>
#include <cuda_bf16.h>
#include <cstdint>

// ESN: h_t = tanh(x_t @ W_in^T + h_{t-1} @ W_res^T); out = h_{T-1} [B,H] fp32.
// B=64, T=512, I=128, H=2048.
//
// Round 17: round-15 chassis (persistent 144 CTAs, 3-term bf16 mma.sync,
// 16 warps 16j x 32b, W in smem, wide full-width reduce, h^T layout,
// ldmatrix.trans, padded flags, all-thread acquire spins) + incremental
// HALF-SLICE staging: hfl is per-jg (16 flags, 8 arrivals); the stager
// copies k-rows 0-127 after the first jg-half's flag, then 128-255 after
// the second — overlapping the copy with reduce stragglers. All 512
// threads on every phase; no extra barriers.

#define BB   64
#define TT   512
#define II   128
#define HH   2048
#define NJG  16
#define NKS  9
#define KC1  256
#define NTHR 512
#define NCTA (NJG * NKS)          // 144
#define ASTRIDE 528               // bytes per j-row of W tiles (512 + 16 pad)
#define TSZA (128 * ASTRIDE)      // 67584 per W term
#define BSTR 144                  // bytes per k-row of v (128 data + 16 pad)
#define TSZB (256 * BSTR)         // 36864 per v term (max 256 k-rows)
#define BOFF (2 * TSZA)
#define SLOT (2 * TSZA)
#define DYN_SMEM (2 * TSZA + 2 * TSZB)   // 208896

// ---------------- device globals ----------------
struct __align__(128) PadFlag { unsigned v; unsigned pad[31]; };

__device__ __align__(16) unsigned char  g_wt[NCTA * SLOT];
__device__ __align__(16) __nv_bfloat16  g_xth[TT * II * BB];   // x^T hi: [t][k][b]
__device__ __align__(16) __nv_bfloat16  g_xtl[TT * II * BB];   // x^T lo
__device__ __align__(16) __nv_bfloat16  g_hth[2][HH * BB];     // h^T hi: [j][b]
__device__ __align__(16) __nv_bfloat16  g_htl[2][HH * BB];     // h^T lo
__device__ float    g_part[2][NKS * NJG * 128 * BB];           // ping-pong by t&1
__device__ PadFlag  g_pcnt[NJG];   // partials stored, per jg (9/step)
__device__ PadFlag  g_hfl[NJG];    // h jg-tile ready, per jg (8/step)

// ---------------- asm helpers ----------------
__device__ __forceinline__ void mma_bf16(float* d, const uint32_t* a,
                                         uint32_t b0, uint32_t b1) {
    asm volatile(
        "mma.sync.aligned.m16n8k16.row.col.f32.bf16.bf16.f32 "
        "{%0,%1,%2,%3}, {%4,%5,%6,%7}, {%8,%9}, {%0,%1,%2,%3};"
        : "+f"(d[0]), "+f"(d[1]), "+f"(d[2]), "+f"(d[3])
        : "r"(a[0]), "r"(a[1]), "r"(a[2]), "r"(a[3]), "r"(b0), "r"(b1));
}
__device__ __forceinline__ void ldmx4(uint32_t* r, uint32_t addr) {
    asm volatile("ldmatrix.sync.aligned.m8n8.x4.shared.b16 {%0,%1,%2,%3}, [%4];"
        : "=r"(r[0]), "=r"(r[1]), "=r"(r[2]), "=r"(r[3]) : "r"(addr));
}
__device__ __forceinline__ void ldmx4t(uint32_t* r, uint32_t addr) {
    asm volatile("ldmatrix.sync.aligned.m8n8.x4.trans.shared.b16 {%0,%1,%2,%3}, [%4];"
        : "=r"(r[0]), "=r"(r[1]), "=r"(r[2]), "=r"(r[3]) : "r"(addr));
}
__device__ __forceinline__ uint32_t smem_u32(const void* p) {
    uint32_t a;
    asm("{ .reg .u64 t; cvta.to.shared.u64 t, %1; cvt.u32.u64 %0, t; }"
        : "=r"(a) : "l"(p));
    return a;
}
__device__ __forceinline__ void flag_add(unsigned* p) {
    asm volatile("red.release.gpu.global.add.u32 [%0], 1;" :: "l"(p) : "memory");
}
__device__ __forceinline__ void spin_ge(unsigned* c, unsigned tgt) {
    unsigned v;
    do {
        asm volatile("ld.acquire.gpu.global.u32 %0, [%1];"
                     : "=r"(v) : "l"(c) : "memory");
    } while (v < tgt);
}

// ---------------- prep ----------------
__global__ void esn_prep_w(const float* __restrict__ Win, const float* __restrict__ Wres) {
    const int total = HH * (II + HH);
    for (int idx = blockIdx.x * blockDim.x + threadIdx.x; idx < total;
         idx += gridDim.x * blockDim.x) {
        int j = idx / (II + HH);
        int k = idx % (II + HH);
        int jg = j >> 7, jl = j & 127;
        int ks, kl;
        float w;
        if (k < II) { ks = 0; kl = k; w = Win[j * II + k]; }
        else { int kk = k - II; ks = 1 + (kk >> 8); kl = kk & 255; w = Wres[j * HH + kk]; }
        __nv_bfloat16 hi = __float2bfloat16(w);
        float r = w - __bfloat162float(hi);
        __nv_bfloat16 lo = __float2bfloat16(r);
        unsigned base = (unsigned)(jg * NKS + ks) * SLOT + (unsigned)jl * ASTRIDE + (unsigned)kl * 2;
        *(__nv_bfloat16*)(g_wt + base)        = hi;
        *(__nv_bfloat16*)(g_wt + base + TSZA) = lo;
    }
}

// x -> transposed [t][k][b] bf16 hi/lo planes
__global__ void esn_prep_x(const float* __restrict__ x) {
    const int total = TT * II * BB;
    for (int idx = blockIdx.x * blockDim.x + threadIdx.x; idx < total;
         idx += gridDim.x * blockDim.x) {
        int b  = idx & (BB - 1);
        int tk = idx / BB;
        int t  = tk / II;
        int k  = tk % II;
        float v = x[(b * TT + t) * II + k];
        __nv_bfloat16 hi = __float2bfloat16(v);
        float r = v - __bfloat162float(hi);
        g_xth[idx] = hi;
        g_xtl[idx] = __float2bfloat16(r);
    }
}

__global__ void esn_cnt0() {
    int i = threadIdx.x;
    if (i < NJG) { g_pcnt[i].v = 0u; g_hfl[i].v = 0u; }
}

// ---------------- persistent kernel ----------------
__global__ __launch_bounds__(NTHR, 1) void esn_run(float* __restrict__ out) {
    extern __shared__ __align__(16) unsigned char sm[];

    const int tid  = threadIdx.x;
    const int wid  = tid >> 5;
    const int l    = tid & 31;
    const int wj   = wid >> 1;            // 0..7: 16-row j band
    const int wb   = wid & 1;             // 0..1: 32-col b half
    const int bid  = blockIdx.x;
    const int jg   = bid / NKS;
    const int ks   = bid % NKS;
    const int KC   = ks ? KC1 : II;
    const int kch  = KC >> 4;             // 8 or 16
    const int chunks = KC * 8;            // 16B chunks (8 per 128B k-row)

    const uint32_t smA = smem_u32(sm);
    const uint32_t smB = smA + BOFF;

    const uint32_t aA = smA + (uint32_t)(wj * 16 + ((l >> 3) & 1) * 8 + (l & 7)) * ASTRIDE
                            + (uint32_t)(l >> 4) * 16;
    const uint32_t aB = smB + (uint32_t)((l & 7) + ((l >> 3) & 1) * 8) * BSTR
                            + (uint32_t)(l >> 4) * 16 + (uint32_t)wb * 64;

    // ---- load W slot (hi + lo) into smem once ----
    {
        const uint4* src = (const uint4*)(g_wt + (unsigned)(jg * NKS + ks) * SLOT);
        uint4* dst = (uint4*)sm;
        for (int i = tid; i < SLOT / 16; i += NTHR) dst[i] = src[i];
    }

    // reduce-role constants (bid 0..127): 16j x 64b tile
    const int r_jg = bid >> 3;
    const int r_8  = bid & 7;
    const int jt   = tid >> 5;             // 0..15
    const int b2   = (tid & 31) * 2;       // 0..62

    // ---- stage v_0: ks==0 from x^T[0], else zeros (h_{-1} = 0) ----
    if (ks == 0) {
        for (int i = tid; i < chunks; i += NTHR) {
            int k = i >> 3, c = i & 7;
            uint32_t d = (uint32_t)(BOFF + k * BSTR + c * 16);
            int e = k * BB + c * 8;
            *(uint4*)(sm + d)        = *(const uint4*)(g_xth + e);
            *(uint4*)(sm + d + TSZB) = *(const uint4*)(g_xtl + e);
        }
    } else {
        const uint4 z = make_uint4(0u, 0u, 0u, 0u);
        for (int i = tid; i < chunks; i += NTHR) {
            int k = i >> 3, c = i & 7;
            uint32_t d = (uint32_t)(BOFF + k * BSTR + c * 16);
            *(uint4*)(sm + d)        = z;
            *(uint4*)(sm + d + TSZB) = z;
        }
    }
    __syncthreads();

    for (int t = 0; t < TT; t++) {
        // ---- MMA: warp = 16j x 32b; 3 terms (Ah*Bh + Ah*Bl + Al*Bh) ----
        float acc[4][4];
#pragma unroll
        for (int nf = 0; nf < 4; nf++)
#pragma unroll
            for (int i = 0; i < 4; i++) acc[nf][i] = 0.0f;

#pragma unroll 4
        for (int kc = 0; kc < kch; kc++) {
            const uint32_t kaA = (uint32_t)kc * 32;
            const uint32_t kaB = (uint32_t)kc * (16 * BSTR);
            uint32_t Ah[4], Al[4], Bh[2][4], Bl[2][4];
            ldmx4(Ah, aA + kaA);
            ldmx4(Al, aA + TSZA + kaA);
            ldmx4t(Bh[0], aB + kaB);
            ldmx4t(Bh[1], aB + kaB + 32);
            ldmx4t(Bl[0], aB + TSZB + kaB);
            ldmx4t(Bl[1], aB + TSZB + kaB + 32);
#pragma unroll
            for (int nf = 0; nf < 4; nf++) {
                const int ni = nf >> 1, h8 = (nf & 1) * 2;
                mma_bf16(acc[nf], Ah, Bh[ni][h8], Bh[ni][h8 + 1]);
                mma_bf16(acc[nf], Ah, Bl[ni][h8], Bl[ni][h8 + 1]);
                mma_bf16(acc[nf], Al, Bh[ni][h8], Bh[ni][h8 + 1]);
            }
        }

        // ---- partial stores (.cg) into ping-pong buffer: P[jl*64 + b] ----
        {
            float* P = g_part[t & 1] + (unsigned)(ks * NJG + jg) * (128 * BB);
            const int j0 = wj * 16 + (l >> 2);
            const int bc = (l & 3) * 2;
#pragma unroll
            for (int nf = 0; nf < 4; nf++) {
                const int b = wb * 32 + nf * 8 + bc;
                __stcg((float2*)&P[j0 * BB + b],       make_float2(acc[nf][0], acc[nf][1]));
                __stcg((float2*)&P[(j0 + 8) * BB + b], make_float2(acc[nf][2], acc[nf][3]));
            }
        }
        __syncthreads();                        // all P stores + all v reads done
        if (tid == 0) flag_add(&g_pcnt[jg].v);

        // ---- reduce role (bid 0..127): 16j x 64b tile, full 512-thread width ----
        if (bid < 128) {
            spin_ge(&g_pcnt[r_jg].v, 9u * (t + 1));   // acquire orders my loads

            const unsigned o = (unsigned)((r_8 * 16 + jt) * 64 + b2);
            float s0 = 0.f, s1 = 0.f;
            const float* Pb = g_part[t & 1];
#pragma unroll
            for (int kr = 0; kr < NKS; kr++) {
                const float2 v = __ldcg((const float2*)
                    (Pb + (unsigned)(kr * NJG + r_jg) * (128 * BB) + o));
                s0 += v.x; s1 += v.y;
            }
            s0 = tanhf(s0); s1 = tanhf(s1);

            __nv_bfloat16* hh = g_hth[t & 1];
            __nv_bfloat16* hl = g_htl[t & 1];
            const int jglob = r_jg * 128 + r_8 * 16 + jt;
            const unsigned ho = (unsigned)(jglob * BB + b2);
            __nv_bfloat162 h2 = __floats2bfloat162_rn(s0, s1);
            float r0 = s0 - __bfloat162float(__low2bfloat16(h2));
            float r1 = s1 - __bfloat162float(__high2bfloat16(h2));
            __nv_bfloat162 l2 = __floats2bfloat162_rn(r0, r1);
            __stcg((unsigned*)(hh + ho), *(unsigned*)&h2);
            __stcg((unsigned*)(hl + ho), *(unsigned*)&l2);
            if (t == TT - 1) {                  // one-time scattered out store
                out[b2 * HH + jglob]       = s0;
                out[(b2 + 1) * HH + jglob] = s1;
            }
            __syncthreads();                    // all h stores done before flag
            if (tid == 0) flag_add(&g_hfl[r_jg].v);   // per-jg, 8 arrivals/step
        }

        // ---- stage v_{t+1}: incremental jg-half copies, full width ----
        if (t + 1 < TT) {
            // P WAR: reducers of my jg done reading P[(t+1)&1] (step t-1)
            if (t >= 1) spin_ge(&g_hfl[jg].v, 8u * t);

            if (ks == 0) {
                const __nv_bfloat16* xh = g_xth + (t + 1) * (II * BB);
                const __nv_bfloat16* xl = g_xtl + (t + 1) * (II * BB);
                for (int i = tid; i < chunks; i += NTHR) {
                    int k = i >> 3, c = i & 7;
                    uint32_t d = (uint32_t)(BOFF + k * BSTR + c * 16);
                    int e = k * BB + c * 8;
                    *(uint4*)(sm + d)        = *(const uint4*)(xh + e);
                    *(uint4*)(sm + d + TSZB) = *(const uint4*)(xl + e);
                }
            } else {
                const int sl = ks - 1;            // slice index (2 jg tiles)
#pragma unroll
                for (int half = 0; half < 2; half++) {
                    // RAW: this jg-half's 8 reducers done for step t
                    spin_ge(&g_hfl[2 * sl + half].v, 8u * (t + 1));
                    const __nv_bfloat16* hh = g_hth[t & 1] + (2 * sl + half) * (128 * BB);
                    const __nv_bfloat16* hl = g_htl[t & 1] + (2 * sl + half) * (128 * BB);
                    for (int i = tid; i < 1024; i += NTHR) {   // 128 rows x 8 chunks
                        int k = i >> 3, c = i & 7;
                        uint32_t d = (uint32_t)(BOFF + (half * 128 + k) * BSTR + c * 16);
                        int e = k * BB + c * 8;
                        *(uint4*)(sm + d)        = __ldcg((const uint4*)(hh + e));
                        *(uint4*)(sm + d + TSZB) = __ldcg((const uint4*)(hl + e));
                    }
                }
            }
            __syncthreads();                    // v staged before next MMA
        }
    }
}

// ---------------- launcher ----------------
extern "C" void kernel_launch(void* const* d_in, const int* in_sizes, int n_in,
                              void* d_out, int out_size)
{
    const float* x    = (const float*)d_in[0];
    const float* Win  = (const float*)d_in[1];
    const float* Wres = (const float*)d_in[2];
    float* out = (float*)d_out;

    cudaFuncSetAttribute(esn_run, cudaFuncAttributeMaxDynamicSharedMemorySize, DYN_SMEM);

    esn_prep_w<<<2048, 256>>>(Win, Wres);
    esn_prep_x<<<2048, 256>>>(x);
    esn_cnt0<<<1, 32>>>();
    esn_run<<<NCTA, NTHR, DYN_SMEM>>>(out);
}